// round 1
// baseline (speedup 1.0000x reference)
#include <cuda_runtime.h>
#include <cuda_bf16.h>
#include <math.h>

#define B_     64
#define C_     256
#define L_     4096
#define HEADS_ 8
#define Q_     16
#define D_     32      // C_/HEADS_
#define HQ_    128     // HEADS_*Q_
#define FH_    512
#define EPS_   1e-6f

// ---------------- scratch (device globals; no runtime allocation) ----------------
__device__ float g_mu  [B_ * L_];                 // 1 MB
__device__ float g_rsig[B_ * L_];                 // 1 MB
__device__ float g_attn[(size_t)B_ * HQ_ * L_];   // 134 MB: logits, then softmax weights in-place
__device__ float g_P   [(size_t)B_ * HQ_ * C_];   // 8 MB : pooled normalized features
__device__ float g_Afl [(size_t)B_ * HQ_ * D_];   // 1 MB : A flattened [B, 4096] (h*512+q*32+d)

// =====================================================================
// K1: per-(b,l) layernorm statistics over channel dim
// =====================================================================
__global__ __launch_bounds__(256) void k_stats(const float* __restrict__ x) {
    int idx = blockIdx.x * 256 + threadIdx.x;       // over B_*L_
    int b = idx >> 12;
    int l = idx & (L_ - 1);
    const float* xp = x + (size_t)b * C_ * L_ + l;
    float s = 0.f, s2 = 0.f;
#pragma unroll 8
    for (int c = 0; c < C_; c++) {
        float v = __ldg(xp + (size_t)c * L_);
        s  += v;
        s2 += v * v;
    }
    float mu  = s * (1.f / C_);
    float var = s2 * (1.f / C_) - mu * mu;
    g_mu[idx]   = mu;
    g_rsig[idx] = rsqrtf(var + EPS_);
}

// =====================================================================
// K2: per-(b,h) CTA: logits[q,l] = attn_w_h @ xn_h  (online softmax
// stats per q-row, then in-place normalize -> softmax weights)
// =====================================================================
__global__ __launch_bounds__(256) void k_logits(const float* __restrict__ x,
                                                const float* __restrict__ gamma,
                                                const float* __restrict__ beta,
                                                const float* __restrict__ attn_w) {
    const int h = blockIdx.x;
    const int b = blockIdx.y;
    const int t = threadIdx.x;

    __shared__ float sw[Q_][D_];
    __shared__ float sg[D_], sb[D_];
    __shared__ float rm[256], rs[256];
    __shared__ float sM[Q_], sSinv[Q_];

    for (int i = t; i < Q_ * D_; i += 256) sw[i / D_][i % D_] = attn_w[h * Q_ * D_ + i];
    if (t < D_) { sg[t] = gamma[h * D_ + t]; sb[t] = beta[h * D_ + t]; }
    __syncthreads();

    float m[Q_], ssum[Q_];
#pragma unroll
    for (int q = 0; q < Q_; q++) { m[q] = -3.0e38f; ssum[q] = 0.f; }

    const float* xb = x + ((size_t)b * C_ + (size_t)h * D_) * L_;
    float* lg = g_attn + (size_t)(b * HQ_ + h * Q_) * L_;

    for (int it = 0; it < L_ / 256; it++) {
        int l = it * 256 + t;
        float mu = g_mu[b * L_ + l];
        float rg = g_rsig[b * L_ + l];
        float xv[D_];
#pragma unroll
        for (int j = 0; j < D_; j++)
            xv[j] = (__ldg(xb + (size_t)j * L_ + l) - mu) * rg * sg[j] + sb[j];
#pragma unroll
        for (int q = 0; q < Q_; q++) {
            float acc = 0.f;
#pragma unroll
            for (int j = 0; j < D_; j++) acc += sw[q][j] * xv[j];
            lg[(size_t)q * L_ + l] = acc;
            float mo = m[q];
            float mn = fmaxf(mo, acc);
            ssum[q] = ssum[q] * __expf(mo - mn) + __expf(acc - mn);
            m[q] = mn;
        }
    }

    // block reduce (M, S) per q
    for (int q = 0; q < Q_; q++) {
        rm[t] = m[q]; rs[t] = ssum[q];
        __syncthreads();
        for (int off = 128; off > 0; off >>= 1) {
            if (t < off) {
                float m1 = rm[t], m2 = rm[t + off];
                float mn = fmaxf(m1, m2);
                rs[t] = rs[t] * __expf(m1 - mn) + rs[t + off] * __expf(m2 - mn);
                rm[t] = mn;
            }
            __syncthreads();
        }
        if (t == 0) { sM[q] = rm[0]; sSinv[q] = 1.f / rs[0]; }
        __syncthreads();
    }

    // in-place normalize: logits -> softmax weights (same thread re-reads its own writes)
    for (int it = 0; it < L_ / 256; it++) {
        int l = it * 256 + t;
#pragma unroll
        for (int q = 0; q < Q_; q++) {
            float v = lg[(size_t)q * L_ + l];
            lg[(size_t)q * L_ + l] = __expf(v - sM[q]) * sSinv[q];
        }
    }
}

// =====================================================================
// K3: P[b, hq, c] = sum_l Aw[b,hq,l] * xn[b,c,l]
// fp32 tiled GEMM: BM=128, BN=64, BK=16, 256 threads, 8x4 microtile.
// xn is materialized on-the-fly from x, mu, rsig, gamma, beta.
// =====================================================================
__global__ __launch_bounds__(256) void k_pool(const float* __restrict__ x,
                                              const float* __restrict__ gamma,
                                              const float* __restrict__ beta) {
    const int b  = blockIdx.y;
    const int c0 = blockIdx.x * 64;
    const int t  = threadIdx.x;
    const int tx = t & 15;      // n
    const int ty = t >> 4;      // m

    __shared__ float As[16][128];
    __shared__ float Bs[16][68];

    float acc[8][4];
#pragma unroll
    for (int i = 0; i < 8; i++)
#pragma unroll
        for (int j = 0; j < 4; j++) acc[i][j] = 0.f;

    const float* Ab = g_attn + (size_t)b * HQ_ * L_;
    const float* Xb = x + (size_t)b * C_ * L_;

    const int arow = t >> 2;          // 0..63
    const int akc  = (t & 3) * 4;     // 0,4,8,12

    const int   cload = c0 + arow;
    const float gl = gamma[cload];
    const float bl = beta[cload];

    for (int l0 = 0; l0 < L_; l0 += 16) {
        // A tile: rows arow, arow+64
#pragma unroll
        for (int rr = 0; rr < 2; rr++) {
            int mrow = arow + rr * 64;
            float4 v = *(const float4*)(Ab + (size_t)mrow * L_ + l0 + akc);
            As[akc + 0][mrow] = v.x;
            As[akc + 1][mrow] = v.y;
            As[akc + 2][mrow] = v.z;
            As[akc + 3][mrow] = v.w;
        }
        // B tile: xn[c0+arow][l0+akc..+3]
        {
            float4 v   = *(const float4*)(Xb + (size_t)cload * L_ + l0 + akc);
            int    li  = b * L_ + l0 + akc;
            float4 mu4 = *(const float4*)(g_mu + li);
            float4 rs4 = *(const float4*)(g_rsig + li);
            Bs[akc + 0][arow] = (v.x - mu4.x) * rs4.x * gl + bl;
            Bs[akc + 1][arow] = (v.y - mu4.y) * rs4.y * gl + bl;
            Bs[akc + 2][arow] = (v.z - mu4.z) * rs4.z * gl + bl;
            Bs[akc + 3][arow] = (v.w - mu4.w) * rs4.w * gl + bl;
        }
        __syncthreads();
#pragma unroll
        for (int kk = 0; kk < 16; kk++) {
            float4 a0 = *(const float4*)&As[kk][ty * 8];
            float4 a1 = *(const float4*)&As[kk][ty * 8 + 4];
            float4 b0 = *(const float4*)&Bs[kk][tx * 4];
            float av[8] = {a0.x, a0.y, a0.z, a0.w, a1.x, a1.y, a1.z, a1.w};
            float bv[4] = {b0.x, b0.y, b0.z, b0.w};
#pragma unroll
            for (int i = 0; i < 8; i++)
#pragma unroll
                for (int j = 0; j < 4; j++) acc[i][j] += av[i] * bv[j];
        }
        __syncthreads();
    }

    float* Pb = g_P + (size_t)b * HQ_ * C_;
#pragma unroll
    for (int i = 0; i < 8; i++)
#pragma unroll
        for (int j = 0; j < 4; j++)
            Pb[(size_t)(ty * 8 + i) * C_ + c0 + tx * 4 + j] = acc[i][j];
}

// =====================================================================
// K4a: A[b,h,q,d] = sum_c val_w[h*32+d, c] * P[b,h*16+q, c] + val_b
//      -> g_Afl[b, h*512 + q*32 + d]
// =====================================================================
__global__ __launch_bounds__(256) void k_aproj(const float* __restrict__ val_w,
                                               const float* __restrict__ val_b) {
    const int h = blockIdx.x;
    const int b = blockIdx.y;
    const int t = threadIdx.x;

    __shared__ float sP[Q_][C_];        // 16 KB
    __shared__ float sWt[C_][D_];       // 32 KB (transposed: [c][d])

    const float* Pb = g_P + ((size_t)b * HQ_ + h * Q_) * C_;
    for (int i = t; i < Q_ * C_; i += 256) sP[i / C_][i % C_] = Pb[i];
    const float* Wb = val_w + (size_t)(h * D_) * C_;
    for (int i = t; i < D_ * C_; i += 256) sWt[i % C_][i / C_] = Wb[i];
    __syncthreads();

#pragma unroll
    for (int o = t; o < Q_ * D_; o += 256) {
        int q = o >> 5, d = o & 31;
        float acc = val_b[h * D_ + d];
#pragma unroll 8
        for (int c = 0; c < C_; c++) acc += sWt[c][d] * sP[q][c];
        g_Afl[(size_t)b * (HQ_ * D_) + h * (Q_ * D_) + q * D_ + d] = acc;
    }
}

// =====================================================================
// K4b: out init with bias, then out += Afl @ fin_w^T  (K-split + atomics)
// =====================================================================
__global__ __launch_bounds__(256) void k_outinit(float* __restrict__ out,
                                                 const float* __restrict__ fin_b) {
    int i = blockIdx.x * 256 + threadIdx.x;   // B_*FH_
    out[i] = fin_b[i & (FH_ - 1)];
}

__global__ __launch_bounds__(256) void k_final(const float* __restrict__ fin_w,
                                               float* __restrict__ out) {
    const int n0 = blockIdx.x * 64;           // f tile
    const int k0 = blockIdx.y * 512;          // K split
    const int t  = threadIdx.x;
    const int tx = t & 15;
    const int ty = t >> 4;

    __shared__ float As[16][64];
    __shared__ float Bs[16][68];

    float acc[4][4];
#pragma unroll
    for (int i = 0; i < 4; i++)
#pragma unroll
        for (int j = 0; j < 4; j++) acc[i][j] = 0.f;

    const int arow = t >> 2;
    const int akc  = (t & 3) * 4;

    for (int l0 = k0; l0 < k0 + 512; l0 += 16) {
        float4 va = *(const float4*)(g_Afl + (size_t)arow * (HQ_ * D_) + l0 + akc);
        As[akc + 0][arow] = va.x;
        As[akc + 1][arow] = va.y;
        As[akc + 2][arow] = va.z;
        As[akc + 3][arow] = va.w;
        float4 vb = *(const float4*)(fin_w + (size_t)(n0 + arow) * (HQ_ * D_) + l0 + akc);
        Bs[akc + 0][arow] = vb.x;
        Bs[akc + 1][arow] = vb.y;
        Bs[akc + 2][arow] = vb.z;
        Bs[akc + 3][arow] = vb.w;
        __syncthreads();
#pragma unroll
        for (int kk = 0; kk < 16; kk++) {
            float4 a0 = *(const float4*)&As[kk][ty * 4];
            float4 b0 = *(const float4*)&Bs[kk][tx * 4];
            float av[4] = {a0.x, a0.y, a0.z, a0.w};
            float bv[4] = {b0.x, b0.y, b0.z, b0.w};
#pragma unroll
            for (int i = 0; i < 4; i++)
#pragma unroll
                for (int j = 0; j < 4; j++) acc[i][j] += av[i] * bv[j];
        }
        __syncthreads();
    }
#pragma unroll
    for (int i = 0; i < 4; i++)
#pragma unroll
        for (int j = 0; j < 4; j++)
            atomicAdd(&out[(size_t)(ty * 4 + i) * FH_ + n0 + tx * 4 + j], acc[i][j]);
}

// =====================================================================
extern "C" void kernel_launch(void* const* d_in, const int* in_sizes, int n_in,
                              void* d_out, int out_size) {
    const float* x      = (const float*)d_in[0];
    const float* ln_g   = (const float*)d_in[1];
    const float* ln_b   = (const float*)d_in[2];
    const float* attn_w = (const float*)d_in[3];
    const float* val_w  = (const float*)d_in[4];
    const float* val_b  = (const float*)d_in[5];
    const float* fin_w  = (const float*)d_in[6];
    const float* fin_b  = (const float*)d_in[7];
    float* out = (float*)d_out;

    k_stats  <<<(B_ * L_) / 256, 256>>>(x);
    k_logits <<<dim3(HEADS_, B_), 256>>>(x, ln_g, ln_b, attn_w);
    k_pool   <<<dim3(C_ / 64, B_), 256>>>(x, ln_g, ln_b);
    k_aproj  <<<dim3(HEADS_, B_), 256>>>(val_w, val_b);
    k_outinit<<<(B_ * FH_) / 256, 256>>>(out, fin_b);
    k_final  <<<dim3(FH_ / 64, (HQ_ * D_) / 512), 256>>>(fin_w, out);
}

// round 3
// speedup vs baseline: 1.4315x; 1.4315x over previous
#include <cuda_runtime.h>
#include <cuda_bf16.h>
#include <math.h>
#include <stdint.h>

#define B_     64
#define C_     256
#define L_     4096
#define HEADS_ 8
#define Q_     16
#define D_     32      // C_/HEADS_
#define HQ_    128     // HEADS_*Q_
#define FH_    512
#define EPS_   1e-6f

// ---------------- scratch (device globals; no runtime allocation) ----------------
__device__ float g_mu  [B_ * L_];                 // 1 MB
__device__ float g_rsig[B_ * L_];                 // 1 MB
__device__ float g_attn[(size_t)B_ * HQ_ * L_];   // 134 MB: raw logits
__device__ float g_M   [B_ * HQ_];                // softmax row max
__device__ float g_Sinv[B_ * HQ_];                // softmax 1/sum
__device__ float g_P   [(size_t)B_ * HQ_ * C_];   // 8 MB : pooled normalized features
__device__ float g_Afl [(size_t)B_ * HQ_ * D_];   // 1 MB : A flattened [B, 4096]

// ============================ helpers ============================
__device__ __forceinline__ uint32_t f2tf32(float f) {
    uint32_t u;
    asm("cvt.rna.tf32.f32 %0, %1;" : "=r"(u) : "f"(f));
    return u;
}
__device__ __forceinline__ void mma_tf32(float* d, const uint32_t* a, const uint32_t* bb) {
    asm volatile(
        "mma.sync.aligned.m16n8k8.row.col.f32.tf32.tf32.f32 "
        "{%0,%1,%2,%3}, {%4,%5,%6,%7}, {%8,%9}, {%0,%1,%2,%3};"
        : "+f"(d[0]), "+f"(d[1]), "+f"(d[2]), "+f"(d[3])
        : "r"(a[0]), "r"(a[1]), "r"(a[2]), "r"(a[3]), "r"(bb[0]), "r"(bb[1]));
}

// =====================================================================
// K1: per-(b,l) layernorm statistics over channel dim
// =====================================================================
__global__ __launch_bounds__(256) void k_stats(const float* __restrict__ x) {
    int idx = blockIdx.x * 256 + threadIdx.x;       // over B_*L_
    int b = idx >> 12;
    int l = idx & (L_ - 1);
    const float* xp = x + (size_t)b * C_ * L_ + l;
    float s = 0.f, s2 = 0.f;
#pragma unroll 8
    for (int c = 0; c < C_; c++) {
        float v = __ldg(xp + (size_t)c * L_);
        s  += v;
        s2 += v * v;
    }
    float mu  = s * (1.f / C_);
    float var = s2 * (1.f / C_) - mu * mu;
    g_mu[idx]   = mu;
    g_rsig[idx] = rsqrtf(var + EPS_);
}

// =====================================================================
// K2: per-(b,h) CTA: raw logits + per-row (max, 1/sum) for softmax.
// Normalization is fused into k_pool's A producer.
// =====================================================================
__global__ __launch_bounds__(256) void k_logits(const float* __restrict__ x,
                                                const float* __restrict__ gamma,
                                                const float* __restrict__ beta,
                                                const float* __restrict__ attn_w) {
    const int h = blockIdx.x;
    const int b = blockIdx.y;
    const int t = threadIdx.x;

    __shared__ float sw[Q_][D_];
    __shared__ float sg[D_], sb[D_];
    __shared__ float rm[256], rs[256];

    for (int i = t; i < Q_ * D_; i += 256) sw[i / D_][i % D_] = attn_w[h * Q_ * D_ + i];
    if (t < D_) { sg[t] = gamma[h * D_ + t]; sb[t] = beta[h * D_ + t]; }
    __syncthreads();

    float m[Q_], ssum[Q_];
#pragma unroll
    for (int q = 0; q < Q_; q++) { m[q] = -3.0e38f; ssum[q] = 0.f; }

    const float* xb = x + ((size_t)b * C_ + (size_t)h * D_) * L_;
    float* lg = g_attn + (size_t)(b * HQ_ + h * Q_) * L_;

    for (int it = 0; it < L_ / 256; it++) {
        int l = it * 256 + t;
        float mu = g_mu[b * L_ + l];
        float rg = g_rsig[b * L_ + l];
        float xv[D_];
#pragma unroll
        for (int j = 0; j < D_; j++)
            xv[j] = (__ldg(xb + (size_t)j * L_ + l) - mu) * rg * sg[j] + sb[j];
#pragma unroll
        for (int q = 0; q < Q_; q++) {
            float acc = 0.f;
#pragma unroll
            for (int j = 0; j < D_; j++) acc += sw[q][j] * xv[j];
            lg[(size_t)q * L_ + l] = acc;
            float mo = m[q];
            float mn = fmaxf(mo, acc);
            ssum[q] = ssum[q] * __expf(mo - mn) + __expf(acc - mn);
            m[q] = mn;
        }
    }

    for (int q = 0; q < Q_; q++) {
        rm[t] = m[q]; rs[t] = ssum[q];
        __syncthreads();
        for (int off = 128; off > 0; off >>= 1) {
            if (t < off) {
                float m1 = rm[t], m2 = rm[t + off];
                float mn = fmaxf(m1, m2);
                rs[t] = rs[t] * __expf(m1 - mn) + rs[t + off] * __expf(m2 - mn);
                rm[t] = mn;
            }
            __syncthreads();
        }
        if (t == 0) {
            g_M   [b * HQ_ + h * Q_ + q] = rm[0];
            g_Sinv[b * HQ_ + h * Q_ + q] = 1.f / rs[0];
        }
        __syncthreads();
    }
}

// =====================================================================
// K3: P[b, hq, c] = sum_l softmax(Aw)[b,hq,l] * xn[b,c,l]
// mma.sync tf32 (m16n8k8). M=128, N=128 per CTA, K=4096, BK=32,
// double-buffered padded smem, register-staged global pipeline.
// =====================================================================
#define PK_KS    36                        // padded k stride (floats)
#define PK_TILE  (128 * PK_KS)             // 4608 floats per operand tile
#define PK_SMEM_FLOATS (4 * PK_TILE)       // As0 Bs0 As1 Bs1
#define PK_SMEM_BYTES  (PK_SMEM_FLOATS * 4)

__device__ __forceinline__ void pool_compute(const float* __restrict__ As,
                                             const float* __restrict__ Bs,
                                             int warp_m, int warp_n, int lane,
                                             float acc[2][8][4]) {
    const uint32_t* Au = (const uint32_t*)As;
    const uint32_t* Bu = (const uint32_t*)Bs;
    const int lr = lane >> 2;
    const int lc = lane & 3;
#pragma unroll
    for (int ks = 0; ks < 4; ks++) {
        const int k0 = ks * 8;
        uint32_t af[2][4];
#pragma unroll
        for (int mi = 0; mi < 2; mi++) {
            int mb = warp_m * 32 + mi * 16 + lr;
            af[mi][0] = Au[(size_t)mb * PK_KS + k0 + lc];
            af[mi][1] = Au[(size_t)(mb + 8) * PK_KS + k0 + lc];
            af[mi][2] = Au[(size_t)mb * PK_KS + k0 + lc + 4];
            af[mi][3] = Au[(size_t)(mb + 8) * PK_KS + k0 + lc + 4];
        }
        uint32_t bf[8][2];
#pragma unroll
        for (int ni = 0; ni < 8; ni++) {
            int nb = warp_n * 64 + ni * 8 + lr;
            bf[ni][0] = Bu[(size_t)nb * PK_KS + k0 + lc];
            bf[ni][1] = Bu[(size_t)nb * PK_KS + k0 + lc + 4];
        }
#pragma unroll
        for (int mi = 0; mi < 2; mi++)
#pragma unroll
            for (int ni = 0; ni < 8; ni++)
                mma_tf32(acc[mi][ni], af[mi], bf[ni]);
    }
}

__global__ __launch_bounds__(256, 1) void k_pool_mma(const float* __restrict__ x,
                                                     const float* __restrict__ gamma,
                                                     const float* __restrict__ beta) {
    extern __shared__ float sm[];
    float* Atile[2] = { sm,               sm + 2 * PK_TILE };
    float* Btile[2] = { sm + PK_TILE,     sm + 3 * PK_TILE };

    const int b  = blockIdx.y;
    const int c0 = blockIdx.x * 128;
    const int t  = threadIdx.x;
    const int w  = t >> 5;
    const int lane   = t & 31;
    const int warp_m = w & 3;
    const int warp_n = w >> 2;

    const int row  = t >> 1;         // 0..127 (A: hq row, B: c row)
    const int colb = (t & 1) * 16;   // 0 or 16

    const float Mr = g_M   [b * HQ_ + row];
    const float Sr = g_Sinv[b * HQ_ + row];
    const float gl = gamma[c0 + row];
    const float bl = beta [c0 + row];

    const float* Ap  = g_attn + ((size_t)b * HQ_ + row) * L_;
    const float* Xp  = x + ((size_t)(b * C_ + c0 + row)) * L_;
    const float* mup = g_mu   + (size_t)b * L_;
    const float* rsp = g_rsig + (size_t)b * L_;

    float acc[2][8][4];
#pragma unroll
    for (int mi = 0; mi < 2; mi++)
#pragma unroll
        for (int ni = 0; ni < 8; ni++)
#pragma unroll
            for (int j = 0; j < 4; j++) acc[mi][ni][j] = 0.f;

    float4 ar[4], xr[4];

    // ---- producer helpers (inline lambdas via macros) ----
#define POOL_LOAD(CH) do {                                              \
        const int _l = (CH) * 32 + colb;                                \
        _Pragma("unroll")                                               \
        for (int i = 0; i < 4; i++) {                                   \
            ar[i] = *(const float4*)(Ap + _l + i * 4);                  \
            xr[i] = *(const float4*)(Xp + _l + i * 4);                  \
        }                                                               \
    } while (0)

#define POOL_STORE(ST, CH) do {                                         \
        float* _As = Atile[ST];                                         \
        float* _Bs = Btile[ST];                                         \
        const int _l = (CH) * 32 + colb;                                \
        _Pragma("unroll")                                               \
        for (int i = 0; i < 4; i++) {                                   \
            const int col = colb + i * 4;                               \
            float* ap = _As + (size_t)row * PK_KS + col;                \
            ap[0] = __uint_as_float(f2tf32(__expf(ar[i].x - Mr) * Sr)); \
            ap[1] = __uint_as_float(f2tf32(__expf(ar[i].y - Mr) * Sr)); \
            ap[2] = __uint_as_float(f2tf32(__expf(ar[i].z - Mr) * Sr)); \
            ap[3] = __uint_as_float(f2tf32(__expf(ar[i].w - Mr) * Sr)); \
            float4 m4 = *(const float4*)(mup + _l + i * 4);             \
            float4 r4 = *(const float4*)(rsp + _l + i * 4);             \
            float* bp = _Bs + (size_t)row * PK_KS + col;                \
            bp[0] = __uint_as_float(f2tf32((xr[i].x - m4.x) * r4.x * gl + bl)); \
            bp[1] = __uint_as_float(f2tf32((xr[i].y - m4.y) * r4.y * gl + bl)); \
            bp[2] = __uint_as_float(f2tf32((xr[i].z - m4.z) * r4.z * gl + bl)); \
            bp[3] = __uint_as_float(f2tf32((xr[i].w - m4.w) * r4.w * gl + bl)); \
        }                                                               \
    } while (0)

    // prologue: fill both stages
    POOL_LOAD(0); POOL_STORE(0, 0);
    POOL_LOAD(1); POOL_STORE(1, 1);
    __syncthreads();

    const int NCHUNK = L_ / 32;   // 128
    for (int it = 0; it < NCHUNK; it++) {
        const int s = it & 1;
        const bool more = (it + 2 < NCHUNK);
        if (more) POOL_LOAD(it + 2);
        pool_compute(Atile[s], Btile[s], warp_m, warp_n, lane, acc);
        __syncthreads();
        if (more) POOL_STORE(s, it + 2);
    }

    // epilogue
    const int lr = lane >> 2;
    const int lc = lane & 3;
#pragma unroll
    for (int mi = 0; mi < 2; mi++) {
        const int m = warp_m * 32 + mi * 16 + lr;
#pragma unroll
        for (int ni = 0; ni < 8; ni++) {
            const int n = c0 + warp_n * 64 + ni * 8 + lc * 2;
            float* Pp = g_P + ((size_t)b * HQ_ + m) * C_ + n;
            *(float2*)Pp              = make_float2(acc[mi][ni][0], acc[mi][ni][1]);
            *(float2*)(Pp + 8 * C_)   = make_float2(acc[mi][ni][2], acc[mi][ni][3]);
        }
    }
#undef POOL_LOAD
#undef POOL_STORE
}

// =====================================================================
// K4a: A[b,h,q,d] = sum_c val_w[h*32+d, c] * P[b,h*16+q, c] + val_b
// (4 independent accumulators for ILP)
// =====================================================================
__global__ __launch_bounds__(256) void k_aproj(const float* __restrict__ val_w,
                                               const float* __restrict__ val_b) {
    const int h = blockIdx.x;
    const int b = blockIdx.y;
    const int t = threadIdx.x;

    __shared__ float sP[Q_][C_];
    __shared__ float sWt[C_][D_];

    const float* Pb = g_P + ((size_t)b * HQ_ + h * Q_) * C_;
    for (int i = t; i < Q_ * C_; i += 256) sP[i / C_][i % C_] = Pb[i];
    const float* Wb = val_w + (size_t)(h * D_) * C_;
    for (int i = t; i < D_ * C_; i += 256) sWt[i % C_][i / C_] = Wb[i];
    __syncthreads();

#pragma unroll
    for (int o = t; o < Q_ * D_; o += 256) {
        int q = o >> 5, d = o & 31;
        float a0 = 0.f, a1 = 0.f, a2 = 0.f, a3 = 0.f;
#pragma unroll 8
        for (int c = 0; c < C_; c += 4) {
            a0 += sWt[c + 0][d] * sP[q][c + 0];
            a1 += sWt[c + 1][d] * sP[q][c + 1];
            a2 += sWt[c + 2][d] * sP[q][c + 2];
            a3 += sWt[c + 3][d] * sP[q][c + 3];
        }
        g_Afl[(size_t)b * (HQ_ * D_) + h * (Q_ * D_) + q * D_ + d] =
            val_b[h * D_ + d] + ((a0 + a1) + (a2 + a3));
    }
}

// =====================================================================
// K4b: out init with bias, then out += Afl @ fin_w^T
// =====================================================================
__global__ __launch_bounds__(256) void k_outinit(float* __restrict__ out,
                                                 const float* __restrict__ fin_b) {
    int i = blockIdx.x * 256 + threadIdx.x;
    out[i] = fin_b[i & (FH_ - 1)];
}

__global__ __launch_bounds__(256) void k_final(const float* __restrict__ fin_w,
                                               float* __restrict__ out) {
    const int n0 = blockIdx.x * 64;
    const int k0 = blockIdx.y * 512;
    const int t  = threadIdx.x;
    const int tx = t & 15;
    const int ty = t >> 4;

    __shared__ float As[16][64];
    __shared__ float Bs[16][68];

    float acc[4][4];
#pragma unroll
    for (int i = 0; i < 4; i++)
#pragma unroll
        for (int j = 0; j < 4; j++) acc[i][j] = 0.f;

    const int arow = t >> 2;
    const int akc  = (t & 3) * 4;

    for (int l0 = k0; l0 < k0 + 512; l0 += 16) {
        float4 va = *(const float4*)(g_Afl + (size_t)arow * (HQ_ * D_) + l0 + akc);
        As[akc + 0][arow] = va.x;
        As[akc + 1][arow] = va.y;
        As[akc + 2][arow] = va.z;
        As[akc + 3][arow] = va.w;
        float4 vb = *(const float4*)(fin_w + (size_t)(n0 + arow) * (HQ_ * D_) + l0 + akc);
        Bs[akc + 0][arow] = vb.x;
        Bs[akc + 1][arow] = vb.y;
        Bs[akc + 2][arow] = vb.z;
        Bs[akc + 3][arow] = vb.w;
        __syncthreads();
#pragma unroll
        for (int kk = 0; kk < 16; kk++) {
            float4 a0 = *(const float4*)&As[kk][ty * 4];
            float4 b0 = *(const float4*)&Bs[kk][tx * 4];
            float av[4] = {a0.x, a0.y, a0.z, a0.w};
            float bv[4] = {b0.x, b0.y, b0.z, b0.w};
#pragma unroll
            for (int i = 0; i < 4; i++)
#pragma unroll
                for (int j = 0; j < 4; j++) acc[i][j] += av[i] * bv[j];
        }
        __syncthreads();
    }
#pragma unroll
    for (int i = 0; i < 4; i++)
#pragma unroll
        for (int j = 0; j < 4; j++)
            atomicAdd(&out[(size_t)(ty * 4 + i) * FH_ + n0 + tx * 4 + j], acc[i][j]);
}

// =====================================================================
extern "C" void kernel_launch(void* const* d_in, const int* in_sizes, int n_in,
                              void* d_out, int out_size) {
    const float* x      = (const float*)d_in[0];
    const float* ln_g   = (const float*)d_in[1];
    const float* ln_b   = (const float*)d_in[2];
    const float* attn_w = (const float*)d_in[3];
    const float* val_w  = (const float*)d_in[4];
    const float* val_b  = (const float*)d_in[5];
    const float* fin_w  = (const float*)d_in[6];
    const float* fin_b  = (const float*)d_in[7];
    float* out = (float*)d_out;

    static bool attr_done = false;
    if (!attr_done) {
        cudaFuncSetAttribute(k_pool_mma, cudaFuncAttributeMaxDynamicSharedMemorySize,
                             PK_SMEM_BYTES);
        attr_done = true;
    }

    k_stats   <<<(B_ * L_) / 256, 256>>>(x);
    k_logits  <<<dim3(HEADS_, B_), 256>>>(x, ln_g, ln_b, attn_w);
    k_pool_mma<<<dim3(2, B_), 256, PK_SMEM_BYTES>>>(x, ln_g, ln_b);
    k_aproj   <<<dim3(HEADS_, B_), 256>>>(val_w, val_b);
    k_outinit <<<(B_ * FH_) / 256, 256>>>(out, fin_b);
    k_final   <<<dim3(FH_ / 64, (HQ_ * D_) / 512), 256>>>(fin_w, out);
}

// round 4
// speedup vs baseline: 1.7531x; 1.2247x over previous
#include <cuda_runtime.h>
#include <cuda_fp16.h>
#include <math.h>
#include <stdint.h>

#define B_     64
#define C_     256
#define L_     4096
#define HEADS_ 8
#define Q_     16
#define D_     32      // C_/HEADS_
#define HQ_    128     // HEADS_*Q_
#define FH_    512
#define EPS_   1e-6f
#define NCH_   4       // softmax l-chunks
#define KSPLIT 2       // k_pool K split

// ---------------- scratch (device globals) ----------------
__device__ float  g_mu   [B_ * L_];                       // 1 MB
__device__ float  g_rsig [B_ * L_];                       // 1 MB
__device__ __half g_attnh[(size_t)B_ * HQ_ * L_];         // 67 MB fp16 logits
__device__ float  g_Mp   [B_ * HQ_ * NCH_];               // partial max
__device__ float  g_Sp   [B_ * HQ_ * NCH_];               // partial sum
__device__ float  g_Ppart[(size_t)KSPLIT * B_ * HQ_ * C_];// 16 MB partial P
__device__ float  g_Afl  [(size_t)B_ * HQ_ * D_];         // 1 MB

// ============================ helpers ============================
__device__ __forceinline__ uint32_t f2tf32(float f) {
    uint32_t u;
    asm("cvt.rna.tf32.f32 %0, %1;" : "=r"(u) : "f"(f));
    return u;
}
__device__ __forceinline__ void mma_tf32(float* d, const uint32_t* a, const uint32_t* bb) {
    asm volatile(
        "mma.sync.aligned.m16n8k8.row.col.f32.tf32.tf32.f32 "
        "{%0,%1,%2,%3}, {%4,%5,%6,%7}, {%8,%9}, {%0,%1,%2,%3};"
        : "+f"(d[0]), "+f"(d[1]), "+f"(d[2]), "+f"(d[3])
        : "r"(a[0]), "r"(a[1]), "r"(a[2]), "r"(a[3]), "r"(bb[0]), "r"(bb[1]));
}

// =====================================================================
// K1: fused layernorm-stats + logits + partial softmax (M, S).
// grid (NCH_, B_); CTA owns 1024 l's; thread owns 4 l's (float4 lanes).
// =====================================================================
__global__ __launch_bounds__(256) void k_lnlog(const float* __restrict__ x,
                                               const float* __restrict__ gamma,
                                               const float* __restrict__ beta,
                                               const float* __restrict__ attn_w) {
    const int chunk = blockIdx.x;
    const int b     = blockIdx.y;
    const int t     = threadIdx.x;
    const int lane  = t & 31;
    const int wid   = t >> 5;
    const int myl   = chunk * 1024 + t * 4;

    __shared__ float sw[HEADS_][Q_][D_];     // 16 KB
    __shared__ float sg[C_], sbt[C_];
    __shared__ float redm[HQ_][8], reds[HQ_][8];

    for (int i = t; i < HEADS_ * Q_ * D_; i += 256) ((float*)sw)[i] = attn_w[i];
    for (int i = t; i < C_; i += 256) { sg[i] = gamma[i]; sbt[i] = beta[i]; }
    __syncthreads();

    const float* xb = x + (size_t)b * C_ * L_;

    // ---- pass 1: stats over channels ----
    float4 s = {0, 0, 0, 0}, s2 = {0, 0, 0, 0};
#pragma unroll 4
    for (int c = 0; c < C_; c++) {
        float4 v = *(const float4*)(xb + (size_t)c * L_ + myl);
        s.x += v.x; s.y += v.y; s.z += v.z; s.w += v.w;
        s2.x += v.x * v.x; s2.y += v.y * v.y; s2.z += v.z * v.z; s2.w += v.w * v.w;
    }
    float4 mu, rs;
    mu.x = s.x * (1.f / C_); mu.y = s.y * (1.f / C_);
    mu.z = s.z * (1.f / C_); mu.w = s.w * (1.f / C_);
    rs.x = rsqrtf(s2.x * (1.f / C_) - mu.x * mu.x + EPS_);
    rs.y = rsqrtf(s2.y * (1.f / C_) - mu.y * mu.y + EPS_);
    rs.z = rsqrtf(s2.z * (1.f / C_) - mu.z * mu.z + EPS_);
    rs.w = rsqrtf(s2.w * (1.f / C_) - mu.w * mu.w + EPS_);
    *(float4*)(g_mu   + b * L_ + myl) = mu;
    *(float4*)(g_rsig + b * L_ + myl) = rs;

    // ---- pass 2: logits per head + partial softmax ----
    for (int h = 0; h < HEADS_; h++) {
        float4 acc[Q_];
#pragma unroll
        for (int q = 0; q < Q_; q++) acc[q] = make_float4(0.f, 0.f, 0.f, 0.f);
#pragma unroll 4
        for (int c = 0; c < D_; c++) {
            const int cg = h * D_ + c;
            float4 v = *(const float4*)(xb + (size_t)cg * L_ + myl);
            const float g = sg[cg], be = sbt[cg];
            float4 xn;
            xn.x = (v.x - mu.x) * rs.x * g + be;
            xn.y = (v.y - mu.y) * rs.y * g + be;
            xn.z = (v.z - mu.z) * rs.z * g + be;
            xn.w = (v.w - mu.w) * rs.w * g + be;
#pragma unroll
            for (int q = 0; q < Q_; q++) {
                const float w = sw[h][q][c];
                acc[q].x += w * xn.x; acc[q].y += w * xn.y;
                acc[q].z += w * xn.z; acc[q].w += w * xn.w;
            }
        }
#pragma unroll
        for (int q = 0; q < Q_; q++) {
            const int row = h * Q_ + q;
            // store fp16 logits
            union { __half2 h2[2]; uint2 u; } cv;
            cv.h2[0] = __floats2half2_rn(acc[q].x, acc[q].y);
            cv.h2[1] = __floats2half2_rn(acc[q].z, acc[q].w);
            *(uint2*)(g_attnh + ((size_t)(b * HQ_ + row)) * L_ + myl) = cv.u;
            // warp max-reduce, then sum of exp, then warp sum-reduce
            float m = fmaxf(fmaxf(acc[q].x, acc[q].y), fmaxf(acc[q].z, acc[q].w));
#pragma unroll
            for (int off = 16; off > 0; off >>= 1)
                m = fmaxf(m, __shfl_xor_sync(0xffffffffu, m, off));
            float ssum = __expf(acc[q].x - m) + __expf(acc[q].y - m) +
                         __expf(acc[q].z - m) + __expf(acc[q].w - m);
#pragma unroll
            for (int off = 16; off > 0; off >>= 1)
                ssum += __shfl_xor_sync(0xffffffffu, ssum, off);
            if (lane == 0) { redm[row][wid] = m; reds[row][wid] = ssum; }
        }
    }
    __syncthreads();
    if (t < HQ_) {
        float m = redm[t][0];
#pragma unroll
        for (int i = 1; i < 8; i++) m = fmaxf(m, redm[t][i]);
        float ssum = 0.f;
#pragma unroll
        for (int i = 0; i < 8; i++) ssum += reds[t][i] * __expf(redm[t][i] - m);
        g_Mp[(b * HQ_ + t) * NCH_ + chunk] = m;
        g_Sp[(b * HQ_ + t) * NCH_ + chunk] = ssum;
    }
}

// =====================================================================
// K2: P = softmax(Aw) @ xn^T   (mma.sync tf32, fp16 A from gmem)
// grid (2 c-blocks, B_, KSPLIT). M=128, N=128, K=2048 per CTA.
// =====================================================================
#define PK_KS    36
#define PK_TILE  (128 * PK_KS)
#define PK_SMEM_BYTES  (4 * PK_TILE * 4)

__device__ __forceinline__ void pool_compute(const float* __restrict__ As,
                                             const float* __restrict__ Bs,
                                             int warp_m, int warp_n, int lane,
                                             float acc[2][8][4]) {
    const uint32_t* Au = (const uint32_t*)As;
    const uint32_t* Bu = (const uint32_t*)Bs;
    const int lr = lane >> 2;
    const int lc = lane & 3;
#pragma unroll
    for (int ks = 0; ks < 4; ks++) {
        const int k0 = ks * 8;
        uint32_t af[2][4];
#pragma unroll
        for (int mi = 0; mi < 2; mi++) {
            int mb = warp_m * 32 + mi * 16 + lr;
            af[mi][0] = Au[(size_t)mb * PK_KS + k0 + lc];
            af[mi][1] = Au[(size_t)(mb + 8) * PK_KS + k0 + lc];
            af[mi][2] = Au[(size_t)mb * PK_KS + k0 + lc + 4];
            af[mi][3] = Au[(size_t)(mb + 8) * PK_KS + k0 + lc + 4];
        }
        uint32_t bf[8][2];
#pragma unroll
        for (int ni = 0; ni < 8; ni++) {
            int nb = warp_n * 64 + ni * 8 + lr;
            bf[ni][0] = Bu[(size_t)nb * PK_KS + k0 + lc];
            bf[ni][1] = Bu[(size_t)nb * PK_KS + k0 + lc + 4];
        }
#pragma unroll
        for (int mi = 0; mi < 2; mi++)
#pragma unroll
            for (int ni = 0; ni < 8; ni++)
                mma_tf32(acc[mi][ni], af[mi], bf[ni]);
    }
}

__global__ __launch_bounds__(256, 2) void k_pool_mma(const float* __restrict__ x,
                                                     const float* __restrict__ gamma,
                                                     const float* __restrict__ beta) {
    extern __shared__ float sm[];
    float* Atile[2] = { sm,           sm + 2 * PK_TILE };
    float* Btile[2] = { sm + PK_TILE, sm + 3 * PK_TILE };

    const int b  = blockIdx.y;
    const int c0 = blockIdx.x * 128;
    const int z  = blockIdx.z;
    const int LOFF = z * (L_ / KSPLIT);
    const int t  = threadIdx.x;
    const int w  = t >> 5;
    const int lane   = t & 31;
    const int warp_m = w & 3;
    const int warp_n = w >> 2;

    const int row  = t >> 1;
    const int colb = (t & 1) * 16;

    // combine partial softmax stats for this A row
    float Mr = -3.0e38f, Sv = 0.f;
#pragma unroll
    for (int i = 0; i < NCH_; i++) {
        float mi = g_Mp[(b * HQ_ + row) * NCH_ + i];
        float si = g_Sp[(b * HQ_ + row) * NCH_ + i];
        float mn = fmaxf(Mr, mi);
        Sv = Sv * __expf(Mr - mn) + si * __expf(mi - mn);
        Mr = mn;
    }
    const float Sr = 1.f / Sv;

    const float gl = gamma[c0 + row];
    const float bl = beta [c0 + row];

    const __half* Aph = g_attnh + ((size_t)b * HQ_ + row) * L_ + LOFF;
    const float* Xp   = x + ((size_t)(b * C_ + c0 + row)) * L_ + LOFF;
    const float* mup  = g_mu   + (size_t)b * L_ + LOFF;
    const float* rsp  = g_rsig + (size_t)b * L_ + LOFF;

    float acc[2][8][4];
#pragma unroll
    for (int mi = 0; mi < 2; mi++)
#pragma unroll
        for (int ni = 0; ni < 8; ni++)
#pragma unroll
            for (int j = 0; j < 4; j++) acc[mi][ni][j] = 0.f;

    uint2  ar2[4];
    float4 xr[4];

#define POOL_LOAD(CH) do {                                              \
        const int _l = (CH) * 32 + colb;                                \
        _Pragma("unroll")                                               \
        for (int i = 0; i < 4; i++) {                                   \
            ar2[i] = *(const uint2*)(Aph + _l + i * 4);                 \
            xr[i]  = *(const float4*)(Xp + _l + i * 4);                 \
        }                                                               \
    } while (0)

#define POOL_STORE(ST, CH) do {                                         \
        float* _As = Atile[ST];                                         \
        float* _Bs = Btile[ST];                                         \
        const int _l = (CH) * 32 + colb;                                \
        _Pragma("unroll")                                               \
        for (int i = 0; i < 4; i++) {                                   \
            const int col = colb + i * 4;                               \
            float2 f0 = __half22float2(*(__half2*)&ar2[i].x);           \
            float2 f1 = __half22float2(*(__half2*)&ar2[i].y);           \
            float* ap = _As + (size_t)row * PK_KS + col;                \
            ap[0] = __uint_as_float(f2tf32(__expf(f0.x - Mr) * Sr));    \
            ap[1] = __uint_as_float(f2tf32(__expf(f0.y - Mr) * Sr));    \
            ap[2] = __uint_as_float(f2tf32(__expf(f1.x - Mr) * Sr));    \
            ap[3] = __uint_as_float(f2tf32(__expf(f1.y - Mr) * Sr));    \
            float4 m4 = *(const float4*)(mup + _l + i * 4);             \
            float4 r4 = *(const float4*)(rsp + _l + i * 4);             \
            float* bp = _Bs + (size_t)row * PK_KS + col;                \
            bp[0] = __uint_as_float(f2tf32((xr[i].x - m4.x) * r4.x * gl + bl)); \
            bp[1] = __uint_as_float(f2tf32((xr[i].y - m4.y) * r4.y * gl + bl)); \
            bp[2] = __uint_as_float(f2tf32((xr[i].z - m4.z) * r4.z * gl + bl)); \
            bp[3] = __uint_as_float(f2tf32((xr[i].w - m4.w) * r4.w * gl + bl)); \
        }                                                               \
    } while (0)

    POOL_LOAD(0); POOL_STORE(0, 0);
    POOL_LOAD(1); POOL_STORE(1, 1);
    __syncthreads();

    const int NCHUNK = (L_ / KSPLIT) / 32;   // 64
    for (int it = 0; it < NCHUNK; it++) {
        const int s = it & 1;
        const bool more = (it + 2 < NCHUNK);
        if (more) POOL_LOAD(it + 2);
        pool_compute(Atile[s], Btile[s], warp_m, warp_n, lane, acc);
        __syncthreads();
        if (more) POOL_STORE(s, it + 2);
    }

    const int lr = lane >> 2;
    const int lc = lane & 3;
#pragma unroll
    for (int mi = 0; mi < 2; mi++) {
        const int m = warp_m * 32 + mi * 16 + lr;
#pragma unroll
        for (int ni = 0; ni < 8; ni++) {
            const int n = c0 + warp_n * 64 + ni * 8 + lc * 2;
            float* Pp = g_Ppart + (((size_t)z * B_ + b) * HQ_ + m) * C_ + n;
            *(float2*)Pp            = make_float2(acc[mi][ni][0], acc[mi][ni][1]);
            *(float2*)(Pp + 8 * C_) = make_float2(acc[mi][ni][2], acc[mi][ni][3]);
        }
    }
#undef POOL_LOAD
#undef POOL_STORE
}

// =====================================================================
// K3: Afl[b, h*512+q*32+d] = sum_c val_w[h*32+d,c]*(P0+P1)[b,hq,c] + val_b
// warp-per-(b,h) mma.sync tf32 with fp32 compensation (3-term).
// =====================================================================
__global__ __launch_bounds__(256) void k_aproj(const float* __restrict__ val_w,
                                               const float* __restrict__ val_b) {
    const int b    = blockIdx.x;
    const int t    = threadIdx.x;
    const int h    = t >> 5;
    const int lane = t & 31;
    const int lr   = lane >> 2;
    const int lc   = lane & 3;

    const float* P0 = g_Ppart + ((size_t)b * HQ_ + h * Q_) * C_;
    const float* P1 = P0 + (size_t)B_ * HQ_ * C_;
    const float* W  = val_w + (size_t)(h * D_) * C_;

    float acc[4][4];
#pragma unroll
    for (int i = 0; i < 4; i++)
#pragma unroll
        for (int j = 0; j < 4; j++) acc[i][j] = 0.f;

    for (int ks = 0; ks < C_ / 8; ks++) {
        const int k0 = ks * 8;
        float a[4];
        a[0] = P0[(size_t)lr * C_ + k0 + lc]           + P1[(size_t)lr * C_ + k0 + lc];
        a[1] = P0[(size_t)(lr + 8) * C_ + k0 + lc]     + P1[(size_t)(lr + 8) * C_ + k0 + lc];
        a[2] = P0[(size_t)lr * C_ + k0 + lc + 4]       + P1[(size_t)lr * C_ + k0 + lc + 4];
        a[3] = P0[(size_t)(lr + 8) * C_ + k0 + lc + 4] + P1[(size_t)(lr + 8) * C_ + k0 + lc + 4];
        uint32_t ah[4], al[4];
#pragma unroll
        for (int j = 0; j < 4; j++) {
            ah[j] = f2tf32(a[j]);
            al[j] = f2tf32(a[j] - __uint_as_float(ah[j]));
        }
#pragma unroll
        for (int nt = 0; nt < 4; nt++) {
            float b0 = W[(size_t)(nt * 8 + lr) * C_ + k0 + lc];
            float b1 = W[(size_t)(nt * 8 + lr) * C_ + k0 + lc + 4];
            uint32_t bh[2], blo[2];
            bh[0] = f2tf32(b0); blo[0] = f2tf32(b0 - __uint_as_float(bh[0]));
            bh[1] = f2tf32(b1); blo[1] = f2tf32(b1 - __uint_as_float(bh[1]));
            mma_tf32(acc[nt], ah, bh);
            mma_tf32(acc[nt], al, bh);
            mma_tf32(acc[nt], ah, blo);
        }
    }

    float* outb = g_Afl + (size_t)b * (HQ_ * D_) + h * (Q_ * D_);
#pragma unroll
    for (int nt = 0; nt < 4; nt++) {
#pragma unroll
        for (int j = 0; j < 2; j++) {        // row group (q = lr, lr+8)
            const int q = lr + j * 8;
#pragma unroll
            for (int jj = 0; jj < 2; jj++) { // col within pair
                const int d = nt * 8 + lc * 2 + jj;
                outb[q * D_ + d] = acc[nt][j * 2 + jj] + val_b[h * D_ + d];
            }
        }
    }
}

// =====================================================================
// K4: out init with bias, then out += Afl @ fin_w^T
// =====================================================================
__global__ __launch_bounds__(256) void k_outinit(float* __restrict__ out,
                                                 const float* __restrict__ fin_b) {
    int i = blockIdx.x * 256 + threadIdx.x;
    out[i] = fin_b[i & (FH_ - 1)];
}

__global__ __launch_bounds__(256) void k_final(const float* __restrict__ fin_w,
                                               float* __restrict__ out) {
    const int n0 = blockIdx.x * 64;
    const int k0 = blockIdx.y * 512;
    const int t  = threadIdx.x;
    const int tx = t & 15;
    const int ty = t >> 4;

    __shared__ float As[16][64];
    __shared__ float Bs[16][68];

    float acc[4][4];
#pragma unroll
    for (int i = 0; i < 4; i++)
#pragma unroll
        for (int j = 0; j < 4; j++) acc[i][j] = 0.f;

    const int arow = t >> 2;
    const int akc  = (t & 3) * 4;

    for (int l0 = k0; l0 < k0 + 512; l0 += 16) {
        float4 va = *(const float4*)(g_Afl + (size_t)arow * (HQ_ * D_) + l0 + akc);
        As[akc + 0][arow] = va.x;
        As[akc + 1][arow] = va.y;
        As[akc + 2][arow] = va.z;
        As[akc + 3][arow] = va.w;
        float4 vb = *(const float4*)(fin_w + (size_t)(n0 + arow) * (HQ_ * D_) + l0 + akc);
        Bs[akc + 0][arow] = vb.x;
        Bs[akc + 1][arow] = vb.y;
        Bs[akc + 2][arow] = vb.z;
        Bs[akc + 3][arow] = vb.w;
        __syncthreads();
#pragma unroll
        for (int kk = 0; kk < 16; kk++) {
            float4 a0 = *(const float4*)&As[kk][ty * 4];
            float4 b0 = *(const float4*)&Bs[kk][tx * 4];
            float av[4] = {a0.x, a0.y, a0.z, a0.w};
            float bv[4] = {b0.x, b0.y, b0.z, b0.w};
#pragma unroll
            for (int i = 0; i < 4; i++)
#pragma unroll
                for (int j = 0; j < 4; j++) acc[i][j] += av[i] * bv[j];
        }
        __syncthreads();
    }
#pragma unroll
    for (int i = 0; i < 4; i++)
#pragma unroll
        for (int j = 0; j < 4; j++)
            atomicAdd(&out[(size_t)(ty * 4 + i) * FH_ + n0 + tx * 4 + j], acc[i][j]);
}

// =====================================================================
extern "C" void kernel_launch(void* const* d_in, const int* in_sizes, int n_in,
                              void* d_out, int out_size) {
    const float* x      = (const float*)d_in[0];
    const float* ln_g   = (const float*)d_in[1];
    const float* ln_b   = (const float*)d_in[2];
    const float* attn_w = (const float*)d_in[3];
    const float* val_w  = (const float*)d_in[4];
    const float* val_b  = (const float*)d_in[5];
    const float* fin_w  = (const float*)d_in[6];
    const float* fin_b  = (const float*)d_in[7];
    float* out = (float*)d_out;

    cudaFuncSetAttribute(k_pool_mma, cudaFuncAttributeMaxDynamicSharedMemorySize,
                         PK_SMEM_BYTES);

    k_lnlog   <<<dim3(NCH_, B_), 256>>>(x, ln_g, ln_b, attn_w);
    k_pool_mma<<<dim3(2, B_, KSPLIT), 256, PK_SMEM_BYTES>>>(x, ln_g, ln_b);
    k_aproj   <<<B_, 256>>>(val_w, val_b);
    k_outinit <<<(B_ * FH_) / 256, 256>>>(out, fin_b);
    k_final   <<<dim3(FH_ / 64, (HQ_ * D_) / 512), 256>>>(fin_w, out);
}